// round 3
// baseline (speedup 1.0000x reference)
#include <cuda_runtime.h>

#define HH 512
#define WW 512
#define TX 32
#define TY 32
#define GXS 38                   // gate region width (gate x: ox-3 .. ox+34)
#define NTH 384
#define NSTRIP 380               // 38 cols x 10 vertical 4-strips
#define RXW 44                   // res row stride (covers ox-8 .. ox+35, float4 aligned)
#define RYS 42                   // res rows (oy-4 .. oy+37)
#define WXW 52                   // guidance window row stride (covers ox-8 .. ox+43)
#define WYS 42                   // guidance window rows (oy-4 .. oy+37)

__device__ __forceinline__ float4 ld4_guard(const float* __restrict__ plane,
                                            int gy, int gx)
{
    float4 v = make_float4(0.f, 0.f, 0.f, 0.f);
    if ((unsigned)gy < HH) {
        const float* __restrict__ row = plane + (size_t)gy * WW;
        if ((unsigned)gx <= (unsigned)(WW - 4)) {
            v = *reinterpret_cast<const float4*>(row + gx);   // aligned: gx ≡ 0 mod 4
        } else {                                              // edge-column tiles only
            if ((unsigned)(gx + 0) < WW) v.x = __ldg(row + gx + 0);
            if ((unsigned)(gx + 1) < WW) v.y = __ldg(row + gx + 1);
            if ((unsigned)(gx + 2) < WW) v.z = __ldg(row + gx + 2);
            if ((unsigned)(gx + 3) < WW) v.w = __ldg(row + gx + 3);
        }
    }
    return v;
}

__global__ __launch_bounds__(NTH, 2)
void affinity_prop_kernel(const float* __restrict__ guid,
                          const float* __restrict__ blur,
                          float* __restrict__ out)
{
    __shared__ float res[2][RYS * RXW];   // 14.8 KB
    __shared__ float win[2][WYS * WXW];   // 17.5 KB (2 guidance channels at a time)

    const int tid = threadIdx.x;
    const int b   = blockIdx.z;
    const int oy  = blockIdx.y * TY;
    const int ox  = blockIdx.x * TX;

    const float* __restrict__ blurb = blur + (size_t)b * HH * WW;
    const float* __restrict__ guidb = guid + (size_t)b * 8 * HH * WW;

    // ---- Init both result buffers from blur (float4, zero-padded) ----
    #pragma unroll
    for (int i = tid; i < RYS * 11; i += NTH) {
        int wy = i / 11, wc = i % 11;
        float4 v = ld4_guard(blurb, oy - 4 + wy, ox - 8 + 4 * wc);
        *reinterpret_cast<float4*>(&res[0][wy * RXW + 4 * wc]) = v;
        *reinterpret_cast<float4*>(&res[1][wy * RXW + 4 * wc]) = v;
    }

    // ---- Thread -> vertical 4-strip mapping ----
    const bool active = tid < NSTRIP;
    const int  s   = active ? tid : 0;
    const int  sy  = s / GXS;            // strip row 0..9
    const int  sx  = s % GXS;            // gate x 0..37
    const int  x   = ox - 3 + sx;        // global x
    const int  y0  = oy - 3 + sy * 4;    // global y of strip top
    const int  rx  = sx + 5;             // res/win x index (base ox-8)
    const int  ryb = sy * 4 + 1;         // res/win y index of strip top (base oy-4)

    // shifted[i,j] = src[i+di, j+dj]
    const int di[8] = { 1, 1, 1, 0, 0, -1, -1, -1 };
    const int dj[8] = { 1, 0,-1, 1,-1,  1,  0, -1 };

    float g[4][8];
    float asum[4] = {0.f, 0.f, 0.f, 0.f};

    // ---- Stage guidance channels through smem (2 at a time), gather gates ----
    #pragma unroll
    for (int kk = 0; kk < 4; kk++) {
        __syncthreads();                       // win buffers free again
        #pragma unroll
        for (int i = tid; i < 2 * WYS * 13; i += NTH) {
            int kb  = i / (WYS * 13);
            int rem = i - kb * (WYS * 13);
            int wy  = rem / 13, wc = rem % 13;
            const float* __restrict__ plane =
                guidb + (size_t)(2 * kk + kb) * HH * WW;
            float4 v = ld4_guard(plane, oy - 4 + wy, ox - 8 + 4 * wc);
            *reinterpret_cast<float4*>(&win[kb][wy * WXW + 4 * wc]) = v;
        }
        __syncthreads();                       // win ready
        #pragma unroll
        for (int kb = 0; kb < 2; kb++) {
            const int k = 2 * kk + kb;
            #pragma unroll
            for (int r = 0; r < 4; r++) {
                float v = win[kb][(ryb + r + di[k]) * WXW + (rx + dj[k])];
                g[r][k] = v;
                asum[r] += fabsf(v);
            }
        }
    }

    // ---- Normalize gates; OOB pixels come out as all-zero automatically ----
    float bias[4], val[4];
    #pragma unroll
    for (int r = 0; r < 4; r++) {
        float inva = (asum[r] > 0.f) ? (1.0f / asum[r]) : 0.f;
        float gs = 0.f;
        #pragma unroll
        for (int k = 0; k < 8; k++) { g[r][k] *= inva; gs += g[r][k]; }
        float raw = res[0][(ryb + r) * RXW + rx];
        bias[r] = (1.0f - gs) * raw;
        val[r]  = raw;
    }

    // ---- 4 fused propagation iterations ----
    #pragma unroll
    for (int t = 0; t < 4; t++) {
        const float* __restrict__ rc = res[t & 1];

        float L[6], R[6], C[6];
        #pragma unroll
        for (int i = 0; i < 6; i++) {
            L[i] = rc[(ryb - 1 + i) * RXW + rx - 1];
            R[i] = rc[(ryb - 1 + i) * RXW + rx + 1];
        }
        C[0] = rc[(ryb - 1) * RXW + rx];
        C[1] = val[0]; C[2] = val[1]; C[3] = val[2]; C[4] = val[3];
        C[5] = rc[(ryb + 4) * RXW + rx];

        float nv[4];
        #pragma unroll
        for (int r = 0; r < 4; r++) {
            float sacc = bias[r];
            sacc += g[r][0] * R[r + 2];   // ( 1, 1)
            sacc += g[r][1] * C[r + 2];   // ( 1, 0)
            sacc += g[r][2] * L[r + 2];   // ( 1,-1)
            sacc += g[r][3] * R[r + 1];   // ( 0, 1)
            sacc += g[r][4] * L[r + 1];   // ( 0,-1)
            sacc += g[r][5] * R[r];       // (-1, 1)
            sacc += g[r][6] * C[r];       // (-1, 0)
            sacc += g[r][7] * L[r];       // (-1,-1)
            nv[r] = sacc;
        }
        #pragma unroll
        for (int r = 0; r < 4; r++) val[r] = nv[r];

        if (t < 3) {
            float* __restrict__ rn = res[(t & 1) ^ 1];
            if (active) {
                #pragma unroll
                for (int r = 0; r < 4; r++)
                    rn[(ryb + r) * RXW + rx] = val[r];
            }
            __syncthreads();
        }
    }

    // ---- Write inner 32x32 ----
    float* __restrict__ outb = out + (size_t)b * HH * WW;
    #pragma unroll
    for (int r = 0; r < 4; r++) {
        int gy = sy * 4 + r;
        if (active && gy >= 3 && gy < 3 + TY && sx >= 3 && sx < 3 + TX)
            outb[(y0 + r) * WW + x] = val[r];
    }
}

extern "C" void kernel_launch(void* const* d_in, const int* in_sizes, int n_in,
                              void* d_out, int out_size)
{
    const float* guid = (const float*)d_in[0];
    const float* blur = (const float*)d_in[1];
    int gsz = in_sizes[0];
    int bsz = in_sizes[1];
    if (n_in >= 2 && gsz < bsz) {   // defensive: handle swapped order
        const float* tmp = guid; guid = blur; blur = tmp;
        int t = gsz; gsz = bsz; bsz = t;
    }
    int batch = bsz / (HH * WW);

    dim3 grid(WW / TX, HH / TY, batch);
    affinity_prop_kernel<<<grid, NTH>>>(guid, blur, (float*)d_out);
}

// round 4
// speedup vs baseline: 2.0992x; 2.0992x over previous
#include <cuda_runtime.h>

#define HH 512
#define WW 512
#define TX 32
#define TY 32
#define GXS 38                   // gate region width (x: ox-3 .. ox+34)
#define NTH 384
#define NSTRIP 380               // 38 cols x 10 vertical 4-strips
#define RXW 44                   // res row stride (x: ox-8 .. ox+35; float4 aligned)
#define RYS 42                   // res rows (y: oy-4 .. oy+37)

// shifted[i,j] = src[i+di, j+dj]
#define DI0 1
#define DI1 1
#define DI2 1
#define DI3 0
#define DI4 0
#define DI5 (-1)
#define DI6 (-1)
#define DI7 (-1)
#define DJ0 1
#define DJ1 0
#define DJ2 (-1)
#define DJ3 1
#define DJ4 (-1)
#define DJ5 1
#define DJ6 0
#define DJ7 (-1)

// ============================================================================
// Interior tiles: no bounds checks anywhere.
// ============================================================================
__global__ __launch_bounds__(NTH, 3)
void affinity_interior(const float* __restrict__ guid,
                       const float* __restrict__ blur,
                       float* __restrict__ out)
{
    __shared__ float res[2][RYS * RXW];

    const int tid = threadIdx.x;
    const int b   = blockIdx.z;
    const int oy  = (blockIdx.y + 1) * TY;
    const int ox  = (blockIdx.x + 1) * TX;

    const float* __restrict__ blurb = blur + (size_t)b * HH * WW;
    const float* __restrict__ guidb = guid + (size_t)b * 8 * HH * WW;

    // ---- Init both result buffers (unguarded float4; 44x42 window) ----
    #pragma unroll
    for (int i = tid; i < RYS * 11; i += NTH) {
        int ry = i / 11, c4 = i % 11;
        float4 v = *reinterpret_cast<const float4*>(
            blurb + (size_t)(oy - 4 + ry) * WW + (ox - 8) + 4 * c4);
        *reinterpret_cast<float4*>(&res[0][ry * RXW + 4 * c4]) = v;
        *reinterpret_cast<float4*>(&res[1][ry * RXW + 4 * c4]) = v;
    }

    // ---- Thread -> vertical 4-strip ----
    const bool active = tid < NSTRIP;
    const int  s   = active ? tid : 0;
    const int  sy  = s / GXS;
    const int  sx  = s % GXS;
    const int  x   = ox - 3 + sx;
    const int  y0  = oy - 3 + sy * 4;
    const int  rx  = sx + 5;
    const int  ryb = sy * 4 + 1;

    // ---- Gate loads: 32 LDGs, all constant offsets from one base ----
    float g[4][8];
    {
        const float* __restrict__ gb = guidb + (size_t)y0 * WW + x;
        #pragma unroll
        for (int r = 0; r < 4; r++) {
            const float* __restrict__ gr = gb + r * WW;
            g[r][0] = __ldg(gr + 0 * HH * WW + DI0 * WW + DJ0);
            g[r][1] = __ldg(gr + 1 * HH * WW + DI1 * WW + DJ1);
            g[r][2] = __ldg(gr + 2 * HH * WW + DI2 * WW + DJ2);
            g[r][3] = __ldg(gr + 3 * HH * WW + DI3 * WW + DJ3);
            g[r][4] = __ldg(gr + 4 * HH * WW + DI4 * WW + DJ4);
            g[r][5] = __ldg(gr + 5 * HH * WW + DI5 * WW + DJ5);
            g[r][6] = __ldg(gr + 6 * HH * WW + DI6 * WW + DJ6);
            g[r][7] = __ldg(gr + 7 * HH * WW + DI7 * WW + DJ7);
        }
    }
    __syncthreads();   // init stores complete; gate LDGs in flight overlap this

    // ---- Normalize; bias = (1-gsum)*raw ----
    float bias[4], val[4];
    #pragma unroll
    for (int r = 0; r < 4; r++) {
        float a = 0.f;
        #pragma unroll
        for (int k = 0; k < 8; k++) a += fabsf(g[r][k]);
        float inva = 1.0f / a;
        float gs = 0.f;
        #pragma unroll
        for (int k = 0; k < 8; k++) { g[r][k] *= inva; gs += g[r][k]; }
        float raw = res[0][(ryb + r) * RXW + rx];
        bias[r] = (1.0f - gs) * raw;
        val[r]  = raw;
    }

    // ---- 4 fused iterations ----
    #pragma unroll
    for (int t = 0; t < 4; t++) {
        const float* __restrict__ rc = res[t & 1];

        float L[6], R[6], C[6];
        #pragma unroll
        for (int i = 0; i < 6; i++) {
            L[i] = rc[(ryb - 1 + i) * RXW + rx - 1];
            R[i] = rc[(ryb - 1 + i) * RXW + rx + 1];
        }
        C[0] = rc[(ryb - 1) * RXW + rx];
        C[1] = val[0]; C[2] = val[1]; C[3] = val[2]; C[4] = val[3];
        C[5] = rc[(ryb + 4) * RXW + rx];

        float nv[4];
        #pragma unroll
        for (int r = 0; r < 4; r++) {
            float sacc = bias[r];
            sacc += g[r][0] * R[r + 2];
            sacc += g[r][1] * C[r + 2];
            sacc += g[r][2] * L[r + 2];
            sacc += g[r][3] * R[r + 1];
            sacc += g[r][4] * L[r + 1];
            sacc += g[r][5] * R[r];
            sacc += g[r][6] * C[r];
            sacc += g[r][7] * L[r];
            nv[r] = sacc;
        }
        #pragma unroll
        for (int r = 0; r < 4; r++) val[r] = nv[r];

        if (t < 3) {
            float* __restrict__ rn = res[(t & 1) ^ 1];
            if (active) {
                #pragma unroll
                for (int r = 0; r < 4; r++)
                    rn[(ryb + r) * RXW + rx] = val[r];
            }
            __syncthreads();
        }
    }

    // ---- Write inner 32x32 ----
    float* __restrict__ outb = out + (size_t)b * HH * WW;
    if (active && sx >= 3 && sx < 3 + TX) {
        #pragma unroll
        for (int r = 0; r < 4; r++) {
            int gy = sy * 4 + r;
            if (gy >= 3 && gy < 3 + TY)
                outb[(y0 + r) * WW + x] = val[r];
        }
    }
}

// ============================================================================
// Boundary ring tiles: fully guarded (R2 path), 60 tiles per batch.
// ============================================================================
__global__ __launch_bounds__(NTH, 2)
void affinity_boundary(const float* __restrict__ guid,
                       const float* __restrict__ blur,
                       float* __restrict__ out)
{
    __shared__ float res[2][RYS * RXW];

    const int tid = threadIdx.x;
    const int b   = blockIdx.z;

    int t0 = blockIdx.x, tx, ty;
    if      (t0 < 16) { ty = 0;       tx = t0;      }
    else if (t0 < 32) { ty = 15;      tx = t0 - 16; }
    else if (t0 < 46) { ty = t0 - 31; tx = 0;       }
    else              { ty = t0 - 45; tx = 15;      }
    const int oy = ty * TY;
    const int ox = tx * TX;

    const float* __restrict__ blurb = blur + (size_t)b * HH * WW;
    const float* __restrict__ guidb = guid + (size_t)b * 8 * HH * WW;

    #pragma unroll
    for (int i = tid; i < RYS * RXW; i += NTH) {
        int ry = i / RXW, rc0 = i % RXW;
        int gy = oy + ry - 4, gx = ox + rc0 - 8;
        float v = 0.0f;
        if ((unsigned)gy < HH && (unsigned)gx < WW)
            v = __ldg(&blurb[gy * WW + gx]);
        res[0][i] = v;
        res[1][i] = v;
    }
    __syncthreads();

    const bool active = tid < NSTRIP;
    const int  s   = active ? tid : 0;
    const int  sy  = s / GXS;
    const int  sx  = s % GXS;
    const int  x   = ox - 3 + sx;
    const int  y0  = oy - 3 + sy * 4;
    const int  rx  = sx + 5;
    const int  ryb = sy * 4 + 1;

    const int di[8] = { 1, 1, 1, 0, 0, -1, -1, -1 };
    const int dj[8] = { 1, 0,-1, 1,-1,  1,  0, -1 };

    float g[4][8], bias[4], val[4];

    #pragma unroll
    for (int r = 0; r < 4; r++) {
        int y = y0 + r;
        bool in = active && ((unsigned)y < HH) && ((unsigned)x < WW);
        float a = 0.0f;
        #pragma unroll
        for (int k = 0; k < 8; k++) {
            int yy = y + di[k];
            int xx = x + dj[k];
            float v = 0.0f;
            if (in && (unsigned)yy < HH && (unsigned)xx < WW)
                v = __ldg(&guidb[((size_t)k * HH + yy) * WW + xx]);
            g[r][k] = v;
            a += fabsf(v);
        }
        float inva = in ? (1.0f / a) : 0.0f;
        float gs = 0.0f;
        #pragma unroll
        for (int k = 0; k < 8; k++) { g[r][k] *= inva; gs += g[r][k]; }
        float raw = res[0][(ryb + r) * RXW + rx];
        bias[r] = in ? (1.0f - gs) * raw : 0.0f;
        val[r]  = raw;
    }

    #pragma unroll
    for (int t = 0; t < 4; t++) {
        const float* __restrict__ rc = res[t & 1];

        float L[6], R[6], C[6];
        #pragma unroll
        for (int i = 0; i < 6; i++) {
            L[i] = rc[(ryb - 1 + i) * RXW + rx - 1];
            R[i] = rc[(ryb - 1 + i) * RXW + rx + 1];
        }
        C[0] = rc[(ryb - 1) * RXW + rx];
        C[1] = val[0]; C[2] = val[1]; C[3] = val[2]; C[4] = val[3];
        C[5] = rc[(ryb + 4) * RXW + rx];

        float nv[4];
        #pragma unroll
        for (int r = 0; r < 4; r++) {
            float sacc = bias[r];
            sacc += g[r][0] * R[r + 2];
            sacc += g[r][1] * C[r + 2];
            sacc += g[r][2] * L[r + 2];
            sacc += g[r][3] * R[r + 1];
            sacc += g[r][4] * L[r + 1];
            sacc += g[r][5] * R[r];
            sacc += g[r][6] * C[r];
            sacc += g[r][7] * L[r];
            nv[r] = sacc;
        }
        #pragma unroll
        for (int r = 0; r < 4; r++) val[r] = nv[r];

        if (t < 3) {
            float* __restrict__ rn = res[(t & 1) ^ 1];
            if (active) {
                #pragma unroll
                for (int r = 0; r < 4; r++)
                    rn[(ryb + r) * RXW + rx] = val[r];
            }
            __syncthreads();
        }
    }

    float* __restrict__ outb = out + (size_t)b * HH * WW;
    #pragma unroll
    for (int r = 0; r < 4; r++) {
        int gy = sy * 4 + r;
        if (active && gy >= 3 && gy < 3 + TY && sx >= 3 && sx < 3 + TX) {
            int yy = y0 + r;
            if ((unsigned)yy < HH && (unsigned)x < WW)
                outb[yy * WW + x] = val[r];
        }
    }
}

extern "C" void kernel_launch(void* const* d_in, const int* in_sizes, int n_in,
                              void* d_out, int out_size)
{
    const float* guid = (const float*)d_in[0];
    const float* blur = (const float*)d_in[1];
    int gsz = in_sizes[0];
    int bsz = in_sizes[1];
    if (n_in >= 2 && gsz < bsz) {   // defensive: handle swapped order
        const float* tmp = guid; guid = blur; blur = tmp;
        int t = gsz; gsz = bsz; bsz = t;
    }
    int batch = bsz / (HH * WW);

    dim3 gi(14, 14, batch);
    affinity_interior<<<gi, NTH>>>(guid, blur, (float*)d_out);
    dim3 gb(60, 1, batch);
    affinity_boundary<<<gb, NTH>>>(guid, blur, (float*)d_out);
}

// round 5
// speedup vs baseline: 2.5312x; 1.2058x over previous
#include <cuda_runtime.h>

#define HH 512
#define WW 512
#define TX 32
#define TY 32
#define GXS 38                   // gate region width (x: ox-3 .. ox+34)
#define NTH 384
#define NSTRIP 380               // 38 cols x 10 vertical 4-strips
#define RXW 44                   // res row stride (x: ox-8 .. ox+35; float4 aligned)
#define RYS 42                   // res rows (y: oy-4 .. oy+37)

// shifted[i,j] = src[i+di, j+dj]
__device__ __constant__ int c_di[8] = { 1, 1, 1, 0, 0, -1, -1, -1 };
__device__ __constant__ int c_dj[8] = { 1, 0,-1, 1,-1,  1,  0, -1 };

#define DI0 1
#define DI1 1
#define DI2 1
#define DI3 0
#define DI4 0
#define DI5 (-1)
#define DI6 (-1)
#define DI7 (-1)
#define DJ0 1
#define DJ1 0
#define DJ2 (-1)
#define DJ3 1
#define DJ4 (-1)
#define DJ5 1
#define DJ6 0
#define DJ7 (-1)

__device__ __forceinline__ float4 ld4_guard(const float* __restrict__ plane,
                                            int gy, int gx)
{
    float4 v = make_float4(0.f, 0.f, 0.f, 0.f);
    if ((unsigned)gy < HH) {
        const float* __restrict__ row = plane + (size_t)gy * WW;
        if ((unsigned)gx <= (unsigned)(WW - 4)) {
            v = *reinterpret_cast<const float4*>(row + gx);   // gx ≡ 0 mod 4
        } else {
            if ((unsigned)(gx + 0) < WW) v.x = __ldg(row + gx + 0);
            if ((unsigned)(gx + 1) < WW) v.y = __ldg(row + gx + 1);
            if ((unsigned)(gx + 2) < WW) v.z = __ldg(row + gx + 2);
            if ((unsigned)(gx + 3) < WW) v.w = __ldg(row + gx + 3);
        }
    }
    return v;
}

__global__ __launch_bounds__(NTH, 3)
void affinity_fused(const float* __restrict__ guid,
                    const float* __restrict__ blur,
                    float* __restrict__ out)
{
    __shared__ float res[2][RYS * RXW];

    const int tid = threadIdx.x;
    const int b   = blockIdx.z;
    const int txi = blockIdx.x;
    const int tyi = blockIdx.y;
    const int ox  = txi * TX;
    const int oy  = tyi * TY;
    const bool edge = (txi == 0) | (txi == 15) | (tyi == 0) | (tyi == 15);

    const float* __restrict__ blurb = blur + (size_t)b * HH * WW;
    const float* __restrict__ guidb = guid + (size_t)b * 8 * HH * WW;

    // ---- Thread -> vertical 4-strip ----
    const bool active = tid < NSTRIP;
    const int  s   = active ? tid : 0;
    const int  sy  = s / GXS;
    const int  sx  = s % GXS;
    const int  x   = ox - 3 + sx;        // global x of strip
    const int  y0  = oy - 3 + sy * 4;    // global y of strip top
    const int  rx  = sx + 5;             // res x (base ox-8)
    const int  ryb = sy * 4 + 1;         // res y of strip top (base oy-4)

    float g[4][8];

    if (!edge) {
        // ================= interior fast path (no guards) =================
        #pragma unroll
        for (int i = tid; i < RYS * 11; i += NTH) {
            int ry = i / 11, c4 = i % 11;
            float4 v = *reinterpret_cast<const float4*>(
                blurb + (size_t)(oy - 4 + ry) * WW + (ox - 8) + 4 * c4);
            *reinterpret_cast<float4*>(&res[0][ry * RXW + 4 * c4]) = v;
            *reinterpret_cast<float4*>(&res[1][ry * RXW + 4 * c4]) = v;
        }
        const float* __restrict__ gb = guidb + (size_t)y0 * WW + x;
        #pragma unroll
        for (int r = 0; r < 4; r++) {
            const float* __restrict__ gr = gb + r * WW;
            g[r][0] = __ldg(gr + 0 * HH * WW + DI0 * WW + DJ0);
            g[r][1] = __ldg(gr + 1 * HH * WW + DI1 * WW + DJ1);
            g[r][2] = __ldg(gr + 2 * HH * WW + DI2 * WW + DJ2);
            g[r][3] = __ldg(gr + 3 * HH * WW + DI3 * WW + DJ3);
            g[r][4] = __ldg(gr + 4 * HH * WW + DI4 * WW + DJ4);
            g[r][5] = __ldg(gr + 5 * HH * WW + DI5 * WW + DJ5);
            g[r][6] = __ldg(gr + 6 * HH * WW + DI6 * WW + DJ6);
            g[r][7] = __ldg(gr + 7 * HH * WW + DI7 * WW + DJ7);
        }
    } else {
        // ============ edge path: clamped addresses + float masks ==========
        #pragma unroll
        for (int i = tid; i < RYS * 11; i += NTH) {
            int ry = i / 11, c4 = i % 11;
            float4 v = ld4_guard(blurb, oy - 4 + ry, ox - 8 + 4 * c4);
            *reinterpret_cast<float4*>(&res[0][ry * RXW + 4 * c4]) = v;
            *reinterpret_cast<float4*>(&res[1][ry * RXW + 4 * c4]) = v;
        }
        const int xc = min(max(x, 0), WW - 1);
        #pragma unroll
        for (int r = 0; r < 4; r++) {
            int y  = y0 + r;
            bool pin = ((unsigned)y < HH) & ((unsigned)x < WW);
            #pragma unroll
            for (int k = 0; k < 8; k++) {
                int yy = y + c_di[k];
                int xx = x + c_dj[k];
                int yyc = min(max(yy, 0), HH - 1);
                int xxc = min(max(xx, 0), WW - 1);
                float v = __ldg(&guidb[((size_t)k * HH + yyc) * WW + xxc]);
                bool m = pin & ((unsigned)yy < HH) & ((unsigned)xx < WW);
                g[r][k] = m ? v : 0.0f;
            }
        }
        (void)xc;
    }
    __syncthreads();

    // ---- Normalize; bias = (1-gsum)*raw ----
    float bias[4], val[4];
    #pragma unroll
    for (int r = 0; r < 4; r++) {
        float a = 0.f;
        #pragma unroll
        for (int k = 0; k < 8; k++) a += fabsf(g[r][k]);
        float inva = (a > 0.f) ? (1.0f / a) : 0.0f;
        float gs = 0.f;
        #pragma unroll
        for (int k = 0; k < 8; k++) { g[r][k] *= inva; gs += g[r][k]; }
        float raw = res[0][(ryb + r) * RXW + rx];
        bias[r] = (1.0f - gs) * raw;
        val[r]  = raw;
    }

    // ---- 4 fused iterations ----
    #pragma unroll
    for (int t = 0; t < 4; t++) {
        const float* __restrict__ rc = res[t & 1];

        float L[6], R[6], C[6];
        #pragma unroll
        for (int i = 0; i < 6; i++) {
            L[i] = rc[(ryb - 1 + i) * RXW + rx - 1];
            R[i] = rc[(ryb - 1 + i) * RXW + rx + 1];
        }
        C[0] = rc[(ryb - 1) * RXW + rx];
        C[1] = val[0]; C[2] = val[1]; C[3] = val[2]; C[4] = val[3];
        C[5] = rc[(ryb + 4) * RXW + rx];

        float nv[4];
        #pragma unroll
        for (int r = 0; r < 4; r++) {
            float sacc = bias[r];
            sacc += g[r][0] * R[r + 2];
            sacc += g[r][1] * C[r + 2];
            sacc += g[r][2] * L[r + 2];
            sacc += g[r][3] * R[r + 1];
            sacc += g[r][4] * L[r + 1];
            sacc += g[r][5] * R[r];
            sacc += g[r][6] * C[r];
            sacc += g[r][7] * L[r];
            nv[r] = sacc;
        }
        #pragma unroll
        for (int r = 0; r < 4; r++) val[r] = nv[r];

        if (t < 3) {
            float* __restrict__ rn = res[(t & 1) ^ 1];
            if (active) {
                #pragma unroll
                for (int r = 0; r < 4; r++)
                    rn[(ryb + r) * RXW + rx] = val[r];
            }
            __syncthreads();
        }
    }

    // ---- Write inner 32x32 (always fully in-image: 512/32 = 16 exact) ----
    float* __restrict__ outb = out + (size_t)b * HH * WW;
    if (active && sx >= 3 && sx < 3 + TX) {
        #pragma unroll
        for (int r = 0; r < 4; r++) {
            int gy = sy * 4 + r;
            if (gy >= 3 && gy < 3 + TY)
                outb[(y0 + r) * WW + x] = val[r];
        }
    }
}

extern "C" void kernel_launch(void* const* d_in, const int* in_sizes, int n_in,
                              void* d_out, int out_size)
{
    const float* guid = (const float*)d_in[0];
    const float* blur = (const float*)d_in[1];
    int gsz = in_sizes[0];
    int bsz = in_sizes[1];
    if (n_in >= 2 && gsz < bsz) {   // defensive: handle swapped order
        const float* tmp = guid; guid = blur; blur = tmp;
        int t = gsz; gsz = bsz; bsz = t;
    }
    int batch = bsz / (HH * WW);

    dim3 grid(16, 16, batch);
    affinity_fused<<<grid, NTH>>>(guid, blur, (float*)d_out);
}

// round 6
// speedup vs baseline: 2.7647x; 1.0923x over previous
#include <cuda_runtime.h>
#include <cuda_fp16.h>

#define HH 512
#define WW 512
#define TX 32
#define TY 32
#define GXS 38                   // gate region width (x: ox-3 .. ox+34)
#define NTH 384
#define NSTRIP 380               // 38 cols x 10 vertical 4-strips
#define RXW 44                   // res word columns (x: ox-8 .. ox+35)
#define PR 21                    // pair-rows: 42 rows (y: oy-4 .. oy+37) / 2

// shifted[i,j] = src[i+di, j+dj]
__device__ __constant__ int c_di[8] = { 1, 1, 1, 0, 0, -1, -1, -1 };
__device__ __constant__ int c_dj[8] = { 1, 0,-1, 1,-1,  1,  0, -1 };

#define DI0 1
#define DI1 1
#define DI2 1
#define DI3 0
#define DI4 0
#define DI5 (-1)
#define DI6 (-1)
#define DI7 (-1)
#define DJ0 1
#define DJ1 0
#define DJ2 (-1)
#define DJ3 1
#define DJ4 (-1)
#define DJ5 1
#define DJ6 0
#define DJ7 (-1)

__device__ __forceinline__ unsigned int pack2(float lo, float hi) {
    __half2 h = __halves2half2(__float2half_rn(lo), __float2half_rn(hi));
    return *reinterpret_cast<unsigned int*>(&h);
}
__device__ __forceinline__ float2 unpack2(unsigned int w) {
    __half2 h;
    *reinterpret_cast<unsigned int*>(&h) = w;
    return __half22float2(h);
}

__device__ __forceinline__ float4 ld4_guard(const float* __restrict__ plane,
                                            int gy, int gx)
{
    float4 v = make_float4(0.f, 0.f, 0.f, 0.f);
    if ((unsigned)gy < HH) {
        const float* __restrict__ row = plane + (size_t)gy * WW;
        if ((unsigned)gx <= (unsigned)(WW - 4)) {
            v = *reinterpret_cast<const float4*>(row + gx);   // gx ≡ 0 mod 4
        } else {
            if ((unsigned)(gx + 0) < WW) v.x = __ldg(row + gx + 0);
            if ((unsigned)(gx + 1) < WW) v.y = __ldg(row + gx + 1);
            if ((unsigned)(gx + 2) < WW) v.z = __ldg(row + gx + 2);
            if ((unsigned)(gx + 3) < WW) v.w = __ldg(row + gx + 3);
        }
    }
    return v;
}

__global__ __launch_bounds__(NTH, 3)
void affinity_fused(const float* __restrict__ guid,
                    const float* __restrict__ blur,
                    float* __restrict__ out)
{
    // fp16 exchange buffers: word (p, c) = half2(row 2p, row 2p+1) at col c
    __shared__ unsigned int res[2][PR * RXW];

    const int tid = threadIdx.x;
    const int b   = blockIdx.z;
    const int txi = blockIdx.x;
    const int tyi = blockIdx.y;
    const int ox  = txi * TX;
    const int oy  = tyi * TY;
    const bool edge = (txi == 0) | (txi == 15) | (tyi == 0) | (tyi == 15);

    const float* __restrict__ blurb = blur + (size_t)b * HH * WW;
    const float* __restrict__ guidb = guid + (size_t)b * 8 * HH * WW;

    // ---- Thread -> vertical 4-strip ----
    const bool active = tid < NSTRIP;
    const int  s   = active ? tid : 0;
    const int  sy  = s / GXS;
    const int  sx  = s % GXS;
    const int  x   = ox - 3 + sx;        // global x of strip
    const int  y0  = oy - 3 + sy * 4;    // global y of strip top (row index 4sy+1 in res)
    const int  rx  = sx + 5;             // res col (base ox-8)
    const int  p0  = 2 * sy;             // first pair-row touching the strip

    float g[4][8];

    if (!edge) {
        // ============== interior fast path (no guards) ==============
        #pragma unroll
        for (int i = tid; i < PR * 11; i += NTH) {
            int p = i / 11, q = i % 11;
            const float* __restrict__ base =
                blurb + (size_t)(oy - 4 + 2 * p) * WW + (ox - 8) + 4 * q;
            float4 a  = *reinterpret_cast<const float4*>(base);
            float4 bb = *reinterpret_cast<const float4*>(base + WW);
            unsigned int w0 = pack2(a.x, bb.x), w1 = pack2(a.y, bb.y);
            unsigned int w2 = pack2(a.z, bb.z), w3 = pack2(a.w, bb.w);
            int o = p * RXW + 4 * q;
            res[0][o+0] = w0; res[0][o+1] = w1; res[0][o+2] = w2; res[0][o+3] = w3;
            res[1][o+0] = w0; res[1][o+1] = w1; res[1][o+2] = w2; res[1][o+3] = w3;
        }
        const float* __restrict__ gb = guidb + (size_t)y0 * WW + x;
        #pragma unroll
        for (int r = 0; r < 4; r++) {
            const float* __restrict__ gr = gb + r * WW;
            g[r][0] = __ldg(gr + 0 * HH * WW + DI0 * WW + DJ0);
            g[r][1] = __ldg(gr + 1 * HH * WW + DI1 * WW + DJ1);
            g[r][2] = __ldg(gr + 2 * HH * WW + DI2 * WW + DJ2);
            g[r][3] = __ldg(gr + 3 * HH * WW + DI3 * WW + DJ3);
            g[r][4] = __ldg(gr + 4 * HH * WW + DI4 * WW + DJ4);
            g[r][5] = __ldg(gr + 5 * HH * WW + DI5 * WW + DJ5);
            g[r][6] = __ldg(gr + 6 * HH * WW + DI6 * WW + DJ6);
            g[r][7] = __ldg(gr + 7 * HH * WW + DI7 * WW + DJ7);
        }
    } else {
        // ======== edge path: clamped addresses + float masks ========
        #pragma unroll
        for (int i = tid; i < PR * 11; i += NTH) {
            int p = i / 11, q = i % 11;
            float4 a  = ld4_guard(blurb, oy - 4 + 2 * p, ox - 8 + 4 * q);
            float4 bb = ld4_guard(blurb, oy - 3 + 2 * p, ox - 8 + 4 * q);
            unsigned int w0 = pack2(a.x, bb.x), w1 = pack2(a.y, bb.y);
            unsigned int w2 = pack2(a.z, bb.z), w3 = pack2(a.w, bb.w);
            int o = p * RXW + 4 * q;
            res[0][o+0] = w0; res[0][o+1] = w1; res[0][o+2] = w2; res[0][o+3] = w3;
            res[1][o+0] = w0; res[1][o+1] = w1; res[1][o+2] = w2; res[1][o+3] = w3;
        }
        #pragma unroll
        for (int r = 0; r < 4; r++) {
            int y  = y0 + r;
            bool pin = ((unsigned)y < HH) & ((unsigned)x < WW);
            #pragma unroll
            for (int k = 0; k < 8; k++) {
                int yy = y + c_di[k];
                int xx = x + c_dj[k];
                int yyc = min(max(yy, 0), HH - 1);
                int xxc = min(max(xx, 0), WW - 1);
                float v = __ldg(&guidb[((size_t)k * HH + yyc) * WW + xxc]);
                bool m = pin & ((unsigned)yy < HH) & ((unsigned)xx < WW);
                g[r][k] = m ? v : 0.0f;
            }
        }
    }
    __syncthreads();

    // ---- raw values (fp16-rounded blur) + gate normalization ----
    float raw[4];
    {
        float2 t0 = unpack2(res[0][(p0 + 0) * RXW + rx]);
        float2 t1 = unpack2(res[0][(p0 + 1) * RXW + rx]);
        float2 t2 = unpack2(res[0][(p0 + 2) * RXW + rx]);
        raw[0] = t0.y; raw[1] = t1.x; raw[2] = t1.y; raw[3] = t2.x;
    }
    float bias[4], val[4];
    #pragma unroll
    for (int r = 0; r < 4; r++) {
        float a = 0.f;
        #pragma unroll
        for (int k = 0; k < 8; k++) a += fabsf(g[r][k]);
        float inva = (a > 0.f) ? (1.0f / a) : 0.0f;
        float gs = 0.f;
        #pragma unroll
        for (int k = 0; k < 8; k++) { g[r][k] *= inva; gs += g[r][k]; }
        bias[r] = (1.0f - gs) * raw[r];
        val[r]  = raw[r];
    }

    // ---- 4 fused iterations (fp16 exchange, fp32 compute) ----
    #pragma unroll
    for (int t = 0; t < 4; t++) {
        const unsigned int* __restrict__ rc = res[t & 1];

        float L[6], R[6], C[6];
        {
            float2 a0 = unpack2(rc[(p0 + 0) * RXW + rx - 1]);
            float2 a1 = unpack2(rc[(p0 + 1) * RXW + rx - 1]);
            float2 a2 = unpack2(rc[(p0 + 2) * RXW + rx - 1]);
            L[0] = a0.x; L[1] = a0.y; L[2] = a1.x; L[3] = a1.y; L[4] = a2.x; L[5] = a2.y;
            float2 b0 = unpack2(rc[(p0 + 0) * RXW + rx + 1]);
            float2 b1 = unpack2(rc[(p0 + 1) * RXW + rx + 1]);
            float2 b2 = unpack2(rc[(p0 + 2) * RXW + rx + 1]);
            R[0] = b0.x; R[1] = b0.y; R[2] = b1.x; R[3] = b1.y; R[4] = b2.x; R[5] = b2.y;
            C[0] = unpack2(rc[(p0 + 0) * RXW + rx]).x;      // row 4sy
            C[5] = unpack2(rc[(p0 + 2) * RXW + rx]).y;      // row 4sy+5
        }
        C[1] = val[0]; C[2] = val[1]; C[3] = val[2]; C[4] = val[3];

        float nv[4];
        #pragma unroll
        for (int r = 0; r < 4; r++) {
            float sacc = bias[r];
            sacc += g[r][0] * R[r + 2];
            sacc += g[r][1] * C[r + 2];
            sacc += g[r][2] * L[r + 2];
            sacc += g[r][3] * R[r + 1];
            sacc += g[r][4] * L[r + 1];
            sacc += g[r][5] * R[r];
            sacc += g[r][6] * C[r];
            sacc += g[r][7] * L[r];
            nv[r] = sacc;
        }
        #pragma unroll
        for (int r = 0; r < 4; r++) val[r] = nv[r];

        if (t < 3) {
            if (active) {
                unsigned int* __restrict__ rn = res[(t & 1) ^ 1];
                __half* __restrict__ rh = reinterpret_cast<__half*>(rn);
                // row 4sy+1 -> hi half of word (p0, rx); lo half owned by strip sy-1
                rh[((p0 + 0) * RXW + rx) * 2 + 1] = __float2half_rn(val[0]);
                // rows 4sy+2, 4sy+3 -> full word (p0+1, rx), exclusively owned
                rn[(p0 + 1) * RXW + rx] = pack2(val[1], val[2]);
                // row 4sy+4 -> lo half of word (p0+2, rx)
                rh[((p0 + 2) * RXW + rx) * 2 + 0] = __float2half_rn(val[3]);
            }
            __syncthreads();
        }
    }

    // ---- Write inner 32x32 (full fp32 precision of the last iteration) ----
    float* __restrict__ outb = out + (size_t)b * HH * WW;
    if (active && sx >= 3 && sx < 3 + TX) {
        #pragma unroll
        for (int r = 0; r < 4; r++) {
            int gy = sy * 4 + r;
            if (gy >= 3 && gy < 3 + TY)
                outb[(y0 + r) * WW + x] = val[r];
        }
    }
}

extern "C" void kernel_launch(void* const* d_in, const int* in_sizes, int n_in,
                              void* d_out, int out_size)
{
    const float* guid = (const float*)d_in[0];
    const float* blur = (const float*)d_in[1];
    int gsz = in_sizes[0];
    int bsz = in_sizes[1];
    if (n_in >= 2 && gsz < bsz) {   // defensive: handle swapped order
        const float* tmp = guid; guid = blur; blur = tmp;
        int t = gsz; gsz = bsz; bsz = t;
    }
    int batch = bsz / (HH * WW);

    dim3 grid(16, 16, batch);
    affinity_fused<<<grid, NTH>>>(guid, blur, (float*)d_out);
}